// round 4
// baseline (speedup 1.0000x reference)
#include <cuda_runtime.h>
#include <cstdint>

// Shapes (fixed):
//   x:   [B=8, 37, 37, 384] fp32, channel-last
//   out: [B, 29*384, 37, 37] fp32
//   bins 0..8 : raw shifted by (dy,dx) in {-1,0,1}^2 (row-major), border-clamped
//   bins 9..16: 3x3 avgpool (count_include_pad=False) shifted (dy,dx) in {-3,0,3}^2 \ {0,0}
//   bins 17..28: zeros

#define BATCH 8
#define W 37
#define D 384
#define NBINS 29
#define PLANE (W * W)                    // 1369
#define CHPLANE ((size_t)D * PLANE)      // 525696
#define PADW 44                          // padded row stride (cols -3..39 used = 43)
#define PADH 43
#define PSZ (PADH * PADW)                // 1892
#define SWZ(j) ((j) + ((j) >> 5))        // stride-4 lane pattern -> conflict-free
#define SSZP (PSZ + (PSZ >> 5) + 8)

__device__ __forceinline__ int clampw(int v) { return min(max(v, 0), W - 1); }

// bin offset tables (used only in the small scalar pass)
__device__ __constant__ int c_dy[17] = {-1,-1,-1, 0,0,0, 1,1,1,  -3,-3,-3, 0,0, 3,3,3};
__device__ __constant__ int c_dx[17] = {-1, 0, 1,-1,0,1,-1,0,1,  -3, 0, 3,-3,3,-3,0,3};

__global__ __launch_bounds__(256, 5) void fanout_kernel(const float* __restrict__ in,
                                                        float* __restrict__ out) {
    __shared__ float sr[SSZP];   // padded pre-clamped raw plane
    __shared__ float sp[SSZP];   // padded pre-clamped pooled plane

    const int c = blockIdx.x;
    const int b = blockIdx.y;
    const int tid = threadIdx.x;

    // ---- Load interior of raw plane from channel-last input ----
    const float* src = in + (size_t)b * PLANE * D + c;
    for (int i = tid; i < PLANE; i += 256) {
        int y = i / W, x = i - y * W;
        sr[SWZ((y + 3) * PADW + x + 3)] = src[(size_t)i * D];
    }
    __syncthreads();

    // ---- Fill raw borders by edge replication (pre-applies the clamp) ----
    for (int j = tid; j < PSZ; j += 256) {
        int py = j / PADW, px = j - py * PADW;
        if (px >= PADH) continue;
        int y = py - 3, x = px - 3;
        if ((unsigned)y < (unsigned)W && (unsigned)x < (unsigned)W) continue;
        sr[SWZ(j)] = sr[SWZ((clampw(y) + 3) * PADW + clampw(x) + 3)];
    }
    __syncthreads();

    // ---- 3x3 avg pool (count_include_pad=False) interior ----
    for (int i = tid; i < PLANE; i += 256) {
        int y = i / W, x = i - y * W;
        int y0 = max(y - 1, 0), y1 = min(y + 1, W - 1);
        int x0 = max(x - 1, 0), x1 = min(x + 1, W - 1);
        float s = 0.f;
        for (int yy = y0; yy <= y1; yy++)
            for (int xx = x0; xx <= x1; xx++)
                s += sr[SWZ((yy + 3) * PADW + xx + 3)];
        sp[SWZ((y + 3) * PADW + x + 3)] = s * (1.0f / (float)((y1 - y0 + 1) * (x1 - x0 + 1)));
    }
    __syncthreads();

    // ---- Fill pooled borders ----
    for (int j = tid; j < PSZ; j += 256) {
        int py = j / PADW, px = j - py * PADW;
        if (px >= PADH) continue;
        int y = py - 3, x = px - 3;
        if ((unsigned)y < (unsigned)W && (unsigned)x < (unsigned)W) continue;
        sp[SWZ(j)] = sp[SWZ((clampw(y) + 3) * PADW + clampw(x) + 3)];
    }
    __syncthreads();

    float* const obase = out + ((size_t)(b * NBINS) * D + c) * PLANE;

    // ============ Pass A: row-aligned float4 quads (never cross rows) ============
    // Per row y, aligned start p makes (c + y*37 + x) % 4 == 0 at x = p + 4s.
    for (int t = tid; t < W * 9; t += 256) {
        int y = t / 9, s = t - y * 9;
        int p = (4 - ((c + y) & 3)) & 3;
        int x0 = p + 4 * s;
        if (x0 + 3 > W - 1) continue;               // leftovers go to pass B

        float* op = obase + y * W + x0;             // 16B aligned by construction

        // raw bins: rows dy=-1,0,1; padded row = y+2+r, col start x0+2 (dx=-1)
        int rb = (y + 2) * PADW + (x0 + 2);
        #pragma unroll
        for (int r = 0; r < 3; r++, rb += PADW) {
            float w0 = sr[SWZ(rb)],     w1 = sr[SWZ(rb + 1)], w2 = sr[SWZ(rb + 2)];
            float w3 = sr[SWZ(rb + 3)], w4 = sr[SWZ(rb + 4)], w5 = sr[SWZ(rb + 5)];
            *reinterpret_cast<float4*>(op) = make_float4(w0, w1, w2, w3); op += CHPLANE;
            *reinterpret_cast<float4*>(op) = make_float4(w1, w2, w3, w4); op += CHPLANE;
            *reinterpret_cast<float4*>(op) = make_float4(w2, w3, w4, w5); op += CHPLANE;
        }

        // pooled bins: rows dy=-3,0,3; padded row = y+r*3, col start x0 (dx=-3)
        int pb = y * PADW + x0;
        #pragma unroll
        for (int r = 0; r < 3; r++, pb += 3 * PADW) {
            float w0 = sp[SWZ(pb)],     w1 = sp[SWZ(pb + 1)], w2 = sp[SWZ(pb + 2)];
            float w3 = sp[SWZ(pb + 3)], w4 = sp[SWZ(pb + 4)], w5 = sp[SWZ(pb + 5)];
            float w6 = sp[SWZ(pb + 6)], w7 = sp[SWZ(pb + 7)], w8 = sp[SWZ(pb + 8)];
            float w9 = sp[SWZ(pb + 9)];
            *reinterpret_cast<float4*>(op) = make_float4(w0, w1, w2, w3); op += CHPLANE;
            if (r != 1) {  // center (0,0) bin skipped
                *reinterpret_cast<float4*>(op) = make_float4(w3, w4, w5, w6); op += CHPLANE;
            }
            *reinterpret_cast<float4*>(op) = make_float4(w6, w7, w8, w9); op += CHPLANE;
        }

        // zero bins
        const float4 z = make_float4(0.f, 0.f, 0.f, 0.f);
        #pragma unroll
        for (int k = 0; k < 12; k++) {
            *reinterpret_cast<float4*>(op) = z; op += CHPLANE;
        }
    }

    // ============ Pass B: per-row scalar leftovers (head p + tail) ============
    for (int t = tid; t < W * 5; t += 256) {
        int y = t / 5, j = t - y * 5;
        int p = (4 - ((c + y) & 3)) & 3;
        int nq = (W - p) >> 2, tail = (W - p) & 3;
        int x;
        if (j < p) x = j;
        else { int jj = j - p; if (jj >= tail) continue; x = p + 4 * nq + jj; }

        int base = (y + 3) * PADW + (x + 3);
        float* op = obase + y * W + x;
        #pragma unroll
        for (int bin = 0; bin < 9; bin++) {
            *op = sr[SWZ(base + c_dy[bin] * PADW + c_dx[bin])]; op += CHPLANE;
        }
        #pragma unroll
        for (int bin = 9; bin < 17; bin++) {
            *op = sp[SWZ(base + c_dy[bin] * PADW + c_dx[bin])]; op += CHPLANE;
        }
        #pragma unroll
        for (int bin = 17; bin < NBINS; bin++) {
            *op = 0.f; op += CHPLANE;
        }
    }
}

// ---------------------------------------------------------------------------
extern "C" void kernel_launch(void* const* d_in, const int* in_sizes, int n_in,
                              void* d_out, int out_size) {
    const float* x = (const float*)d_in[0];
    float* out = (float*)d_out;
    dim3 grid(D, BATCH);   // 3072 blocks, one per (channel, batch)
    fanout_kernel<<<grid, 256>>>(x, out);
}

// round 5
// speedup vs baseline: 1.5282x; 1.5282x over previous
#include <cuda_runtime.h>
#include <cstdint>

// Shapes (fixed):
//   x:   [B=8, 37, 37, 384] fp32, channel-last
//   out: [B, 29*384, 37, 37] fp32; out(b,bin,c,y,x) at ((b*29+bin)*384 + c)*1369 + y*37 + x
//   bins 0..8 : raw shifted by (dy,dx) in {-1,0,1}^2 (row-major), border-clamped
//   bins 9..16: 3x3 avgpool (count_include_pad=False) shifted (dy,dx) in {-3,0,3}^2 \ {0,0}
//   bins 17..28: zeros

#define BATCH 8
#define W 37
#define D 384
#define NBINS 29
#define PLANE (W * W)                    // 1369
#define CHPLANE ((size_t)D * PLANE)      // 525696
#define G 4                              // channels per block
#define SWZ(j) ((j) + ((j) >> 5))        // stride-4 lane access -> conflict-free
#define SSZ 1416                         // >= PLANE + (PLANE>>5) + 2 = 1413

__device__ __forceinline__ int clampw(int v) { return min(max(v, 0), W - 1); }

__device__ __constant__ int c_dy[17] = {-1,-1,-1, 0,0,0, 1,1,1,  -3,-3,-3, 0,0, 3,3,3};
__device__ __constant__ int c_dx[17] = {-1, 0, 1,-1,0,1,-1,0,1,  -3, 0, 3,-3,3,-3,0,3};

__global__ __launch_bounds__(256) void fanout_kernel(const float* __restrict__ in,
                                                     float* __restrict__ out) {
    __shared__ float sr[G][SSZ];   // raw planes   (swizzled)
    __shared__ float sp[G][SSZ];   // pooled planes (swizzled)

    const int c0 = blockIdx.x * G;
    const int b  = blockIdx.y;
    const int tid = threadIdx.x;

    // ---- Load 4 channels at once: one float4 LDG per spatial element ----
    const float4* src4 = reinterpret_cast<const float4*>(in + (size_t)b * PLANE * D + c0);
    for (int i = tid; i < PLANE; i += 256) {
        float4 v = src4[(size_t)i * (D / 4)];
        int js = SWZ(i);
        sr[0][js] = v.x; sr[1][js] = v.y; sr[2][js] = v.z; sr[3][js] = v.w;
    }
    __syncthreads();

    // ---- 3x3 avg pool (count_include_pad=False) per channel, in smem ----
    for (int t = tid; t < G * PLANE; t += 256) {
        int g = t / PLANE, i = t - g * PLANE;
        int y = i / W, x = i - y * W;
        int y0 = max(y - 1, 0), y1 = min(y + 1, W - 1);
        int x0 = max(x - 1, 0), x1 = min(x + 1, W - 1);
        float s = 0.f;
        for (int yy = y0; yy <= y1; yy++)
            for (int xx = x0; xx <= x1; xx++)
                s += sr[g][SWZ(yy * W + xx)];
        sp[g][SWZ(i)] = s * (1.0f / (float)((y1 - y0 + 1) * (x1 - x0 + 1)));
    }
    __syncthreads();

    // ---- Gather + store all 29 bins for each of the 4 channels ----
    for (int g = 0; g < G; g++) {
        const float* __restrict__ a_r = sr[g];
        const float* __restrict__ a_p = sp[g];

        const size_t ob = ((size_t)(b * NBINS) * D + (c0 + g)) * PLANE;
        float* const obase = out + ob;
        const int phase = (int)(ob & 3);
        const int head  = (4 - phase) & 3;
        const int nq    = (PLANE - head) >> 2;
        const int tail  = (PLANE - head) & 3;

        // Body: 16B-aligned float4 quads (CHPLANE % 4 == 0 keeps all bins aligned).
        for (int q = tid; q < nq; q += 256) {
            const int i0 = head + 4 * q;
            int y0 = i0 / W, x0 = i0 - y0 * W;

            // Precompute clamped coords per quad element (<= one row crossing).
            int rm1[4], rc[4], rp1[4], rm3[4], rp3[4];
            int km1[4], kc[4], kp1[4], km3[4], kp3[4];
            #pragma unroll
            for (int e = 0; e < 4; e++) {
                int xi = x0 + e, yi = y0;
                if (xi >= W) { xi -= W; yi++; }
                rm1[e] = max(yi - 1, 0) * W;  rc[e] = yi * W;  rp1[e] = min(yi + 1, W - 1) * W;
                rm3[e] = max(yi - 3, 0) * W;  rp3[e] = min(yi + 3, W - 1) * W;
                km1[e] = max(xi - 1, 0);      kc[e] = xi;      kp1[e] = min(xi + 1, W - 1);
                km3[e] = max(xi - 3, 0);      kp3[e] = min(xi + 3, W - 1);
            }

            const int* rowsR[3] = { rm1, rc, rp1 };
            const int* colsR[3] = { km1, kc, kp1 };
            #pragma unroll
            for (int ry = 0; ry < 3; ry++) {
                #pragma unroll
                for (int cx = 0; cx < 3; cx++) {
                    const int bin = ry * 3 + cx;
                    float4 r;
                    r.x = a_r[SWZ(rowsR[ry][0] + colsR[cx][0])];
                    r.y = a_r[SWZ(rowsR[ry][1] + colsR[cx][1])];
                    r.z = a_r[SWZ(rowsR[ry][2] + colsR[cx][2])];
                    r.w = a_r[SWZ(rowsR[ry][3] + colsR[cx][3])];
                    *reinterpret_cast<float4*>(obase + (size_t)bin * CHPLANE + i0) = r;
                }
            }

            const int* rowsP[3] = { rm3, rc, rp3 };
            const int* colsP[3] = { km3, kc, kp3 };
            int bin = 9;
            #pragma unroll
            for (int ry = 0; ry < 3; ry++) {
                #pragma unroll
                for (int cx = 0; cx < 3; cx++) {
                    if (ry == 1 && cx == 1) continue;   // skip center for pooled
                    float4 r;
                    r.x = a_p[SWZ(rowsP[ry][0] + colsP[cx][0])];
                    r.y = a_p[SWZ(rowsP[ry][1] + colsP[cx][1])];
                    r.z = a_p[SWZ(rowsP[ry][2] + colsP[cx][2])];
                    r.w = a_p[SWZ(rowsP[ry][3] + colsP[cx][3])];
                    *reinterpret_cast<float4*>(obase + (size_t)bin * CHPLANE + i0) = r;
                    bin++;
                }
            }

            const float4 z = make_float4(0.f, 0.f, 0.f, 0.f);
            #pragma unroll
            for (int zb = 17; zb < NBINS; zb++)
                *reinterpret_cast<float4*>(obase + (size_t)zb * CHPLANE + i0) = z;
        }

        // Head/tail scalars.
        int si = -1;
        if (tid < head)
            si = tid;
        else if (tid >= 32 && tid < 32 + tail)
            si = head + 4 * nq + (tid - 32);
        if (si >= 0) {
            int y = si / W, x = si - y * W;
            #pragma unroll
            for (int bin = 0; bin < 9; bin++)
                obase[(size_t)bin * CHPLANE + si] =
                    a_r[SWZ(clampw(y + c_dy[bin]) * W + clampw(x + c_dx[bin]))];
            #pragma unroll
            for (int bin = 9; bin < 17; bin++)
                obase[(size_t)bin * CHPLANE + si] =
                    a_p[SWZ(clampw(y + c_dy[bin]) * W + clampw(x + c_dx[bin]))];
            #pragma unroll
            for (int bin = 17; bin < NBINS; bin++)
                obase[(size_t)bin * CHPLANE + si] = 0.f;
        }
    }
}

// ---------------------------------------------------------------------------
extern "C" void kernel_launch(void* const* d_in, const int* in_sizes, int n_in,
                              void* d_out, int out_size) {
    const float* x = (const float*)d_in[0];
    float* out = (float*)d_out;
    dim3 grid(D / G, BATCH);   // 768 blocks
    fanout_kernel<<<grid, 256>>>(x, out);
}

// round 6
// speedup vs baseline: 1.8122x; 1.1859x over previous
#include <cuda_runtime.h>
#include <cstdint>

// Shapes (fixed):
//   x:   [B=8, 37, 37, 384] fp32, channel-last
//   out: [B, 29*384, 37, 37] fp32; out(b,bin,c,y,x) at ((b*29+bin)*384 + c)*1369 + y*37 + x
//   bins 0..8 : raw shifted by (dy,dx) in {-1,0,1}^2 (row-major), border-clamped
//   bins 9..16: 3x3 avgpool (count_include_pad=False) shifted (dy,dx) in {-3,0,3}^2 \ {0,0}
//   bins 17..28: zeros

#define BATCH 8
#define W 37
#define D 384
#define NBINS 29
#define PLANE (W * W)                    // 1369
#define CHPLANE ((size_t)D * PLANE)      // 525696
#define G 2                              // channels per gather block
#define SWZ(j) ((j) + ((j) >> 5))        // stride-4 lane access -> conflict-free
#define SSZ 1416                         // >= PLANE + (PLANE>>5) + 2

#define NGATHER ((D / G) * BATCH)        // 1536
#define NZERO   512
#define NBLOCKS (NGATHER + NZERO)        // 2048; every 4th block (bx%4==3) is a zero block

__device__ __forceinline__ int clampw(int v) { return min(max(v, 0), W - 1); }

// Border-clamped gather from a swizzled smem plane.
__device__ __forceinline__ float gat(const float* a, int y, int x) {
    return a[SWZ(clampw(y) * W + clampw(x))];
}

__device__ __constant__ int c_dy[17] = {-1,-1,-1, 0,0,0, 1,1,1,  -3,-3,-3, 0,0, 3,3,3};
__device__ __constant__ int c_dx[17] = {-1, 0, 1,-1,0,1,-1,0,1,  -3, 0, 3,-3,3,-3,0,3};

__global__ __launch_bounds__(256) void fanout_kernel(const float* __restrict__ in,
                                                     float* __restrict__ out) {
    const int bx  = blockIdx.x;
    const int tid = threadIdx.x;

    // ---------------- Zero blocks: pure-BW fill of bins 17..28 ----------------
    if ((bx & 3) == 3) {
        const int zid = bx >> 2;                       // 0..NZERO-1
        const size_t plane4 = CHPLANE / 4;
        const size_t len4   = 12 * plane4;             // per batch
        const size_t total  = (size_t)BATCH * len4;
        const float4 z = make_float4(0.f, 0.f, 0.f, 0.f);
        float4* out4 = reinterpret_cast<float4*>(out);
        for (size_t idx = (size_t)zid * 256 + tid; idx < total; idx += (size_t)NZERO * 256) {
            size_t b = idx / len4;
            size_t r = idx - b * len4;
            out4[(b * NBINS + 17) * plane4 + r] = z;
        }
        return;
    }

    // ---------------- Gather blocks ----------------
    const int gidx = bx - ((bx + 1) >> 2);             // 0..NGATHER-1 (skip zero blocks)
    const int c0 = (gidx % (D / G)) * G;
    const int b  = gidx / (D / G);

    __shared__ float sr[G][SSZ];
    __shared__ float sp[G][SSZ];

    // Load 2 channels per spatial element with one float2 LDG.
    const float2* src2 = reinterpret_cast<const float2*>(in + (size_t)b * PLANE * D + c0);
    for (int i = tid; i < PLANE; i += 256) {
        float2 v = src2[(size_t)i * (D / 2)];
        int js = SWZ(i);
        sr[0][js] = v.x; sr[1][js] = v.y;
    }
    __syncthreads();

    // 3x3 avg pool (count_include_pad=False) per channel, in smem.
    for (int t = tid; t < G * PLANE; t += 256) {
        int g = t / PLANE, i = t - g * PLANE;
        int y = i / W, x = i - y * W;
        int y0 = max(y - 1, 0), y1 = min(y + 1, W - 1);
        int x0 = max(x - 1, 0), x1 = min(x + 1, W - 1);
        float s = 0.f;
        for (int yy = y0; yy <= y1; yy++)
            for (int xx = x0; xx <= x1; xx++)
                s += sr[g][SWZ(yy * W + xx)];
        sp[g][SWZ(i)] = s * (1.0f / (float)((y1 - y0 + 1) * (x1 - x0 + 1)));
    }
    __syncthreads();

    for (int g = 0; g < G; g++) {
        const float* __restrict__ a_r = sr[g];
        const float* __restrict__ a_p = sp[g];

        const size_t ob = ((size_t)(b * NBINS) * D + (c0 + g)) * PLANE;
        float* const obase = out + ob;
        const int phase = (int)(ob & 3);
        const int head  = (4 - phase) & 3;
        const int nq    = (PLANE - head) >> 2;
        const int tail  = (PLANE - head) & 3;

        // Body: 16B-aligned float4 quads (CHPLANE % 4 == 0 keeps all bins aligned).
        for (int q = tid; q < nq; q += 256) {
            const int i0 = head + 4 * q;
            int y0 = i0 / W, x0 = i0 - y0 * W;
            int ys[4], xs[4];
            #pragma unroll
            for (int e = 0; e < 4; e++) {
                int xi = x0 + e, yi = y0;
                if (xi >= W) { xi -= W; yi++; }       // at most one row crossing
                ys[e] = yi; xs[e] = xi;
            }

            #pragma unroll
            for (int bin = 0; bin < 17; bin++) {
                const float* a = (bin < 9) ? a_r : a_p;
                const int dy = c_dy[bin], dx = c_dx[bin];
                float4 r;
                r.x = gat(a, ys[0] + dy, xs[0] + dx);
                r.y = gat(a, ys[1] + dy, xs[1] + dx);
                r.z = gat(a, ys[2] + dy, xs[2] + dx);
                r.w = gat(a, ys[3] + dy, xs[3] + dx);
                *reinterpret_cast<float4*>(obase + (size_t)bin * CHPLANE + i0) = r;
            }
        }

        // Head/tail scalars.
        int si = -1;
        if (tid < head)
            si = tid;
        else if (tid >= 32 && tid < 32 + tail)
            si = head + 4 * nq + (tid - 32);
        if (si >= 0) {
            int y = si / W, x = si - y * W;
            #pragma unroll
            for (int bin = 0; bin < 17; bin++) {
                const float* a = (bin < 9) ? a_r : a_p;
                obase[(size_t)bin * CHPLANE + si] = gat(a, y + c_dy[bin], x + c_dx[bin]);
            }
        }
    }
}

// ---------------------------------------------------------------------------
extern "C" void kernel_launch(void* const* d_in, const int* in_sizes, int n_in,
                              void* d_out, int out_size) {
    const float* x = (const float*)d_in[0];
    float* out = (float*)d_out;
    fanout_kernel<<<NBLOCKS, 256>>>(x, out);
}

// round 8
// speedup vs baseline: 1.8342x; 1.0121x over previous
#include <cuda_runtime.h>
#include <cstdint>

// Shapes (fixed):
//   x:   [B=8, 37, 37, 384] fp32, channel-last
//   out: [B, 29*384, 37, 37] fp32; out(b,bin,c,y,x) at ((b*29+bin)*384 + c)*1369 + y*37 + x
//   bins 0..8 : raw shifted by (dy,dx) in {-1,0,1}^2 (row-major), border-clamped
//   bins 9..16: 3x3 avgpool (count_include_pad=False) shifted (dy,dx) in {-3,0,3}^2 \ {0,0}
//   bins 17..28: zeros

#define BATCH 8
#define W 37
#define D 384
#define NBINS 29
#define PLANE (W * W)                    // 1369
#define CHPLANE ((size_t)D * PLANE)      // 525696
#define G 2                              // channels per gather block

#define PADW 44                          // padded row stride; used cols 0..42 (x in -3..39)
#define PADH 43
#define PSZ (PADH * PADW)                // 1892
#define SWZ(j) ((j) + ((j) >> 5))        // stride-4 lane access -> conflict-free
#define SPSZ (PSZ + (PSZ >> 5) + 4)      // 1955

#define NGATHER ((D / G) * BATCH)        // 1536
#define NZERO   768
#define NBLOCKS (NGATHER + NZERO)        // 2304; every 3rd block (bx%3==2) is a zero block

__device__ __forceinline__ int clampw(int v) { return min(max(v, 0), W - 1); }

// Padded-plane index for logical (y, x) with y,x possibly in [-3, W+2].
#define PIDX(y, x) (((y) + 3) * PADW + ((x) + 3))

__device__ __constant__ int c_off[17] = {
    // raw bins: dy*PADW + dx for (dy,dx) in {-1,0,1}^2 row-major
    -PADW - 1, -PADW, -PADW + 1,  -1, 0, 1,  PADW - 1, PADW, PADW + 1,
    // pooled bins: (dy,dx) in {-3,0,3}^2 minus center
    -3 * PADW - 3, -3 * PADW, -3 * PADW + 3,  -3, 3,  3 * PADW - 3, 3 * PADW, 3 * PADW + 3
};

__global__ __launch_bounds__(256) void fanout_kernel(const float* __restrict__ in,
                                                     float* __restrict__ out) {
    const int bx  = blockIdx.x;
    const int tid = threadIdx.x;

    // ---------------- Zero blocks: pure-BW fill of bins 17..28 ----------------
    if (bx % 3 == 2) {
        const int zid = bx / 3;                        // 0..NZERO-1
        const size_t plane4 = CHPLANE / 4;
        const size_t len4   = 12 * plane4;             // per batch
        const size_t total  = (size_t)BATCH * len4;
        const float4 z = make_float4(0.f, 0.f, 0.f, 0.f);
        float4* out4 = reinterpret_cast<float4*>(out);
        for (size_t idx = (size_t)zid * 256 + tid; idx < total; idx += (size_t)NZERO * 256) {
            size_t b = idx / len4;
            size_t r = idx - b * len4;
            out4[(b * NBINS + 17) * plane4 + r] = z;
        }
        return;
    }

    // ---------------- Gather blocks ----------------
    const int gidx = bx - bx / 3;                      // 0..NGATHER-1
    const int c0 = (gidx % (D / G)) * G;
    const int b  = gidx / (D / G);

    __shared__ float sr[G][SPSZ];   // padded pre-clamped raw planes
    __shared__ float sp[G][SPSZ];   // padded pre-clamped pooled planes

    // Load interior: 2 channels per spatial element with one float2 LDG.
    const float2* src2 = reinterpret_cast<const float2*>(in + (size_t)b * PLANE * D + c0);
    for (int i = tid; i < PLANE; i += 256) {
        int y = i / W, x = i - y * W;
        float2 v = src2[(size_t)i * (D / 2)];
        int js = SWZ(PIDX(y, x));
        sr[0][js] = v.x; sr[1][js] = v.y;
    }
    __syncthreads();

    // Border-fill raw planes (writes borders only) + 3x3 pool interior (reads interior only).
    for (int t = tid; t < G * PSZ; t += 256) {
        int g = t / PSZ, j = t - g * PSZ;
        int py = j / PADW, px = j - py * PADW;
        if (px > PADH - 1) continue;                   // col 43 unused
        int y = py - 3, x = px - 3;
        if ((unsigned)y < (unsigned)W && (unsigned)x < (unsigned)W) continue;
        sr[g][SWZ(j)] = sr[g][SWZ(PIDX(clampw(y), clampw(x)))];
    }
    for (int t = tid; t < G * PLANE; t += 256) {
        int g = t / PLANE, i = t - g * PLANE;
        int y = i / W, x = i - y * W;
        int y0 = max(y - 1, 0), y1 = min(y + 1, W - 1);
        int x0 = max(x - 1, 0), x1 = min(x + 1, W - 1);
        float s = 0.f;
        for (int yy = y0; yy <= y1; yy++)
            for (int xx = x0; xx <= x1; xx++)
                s += sr[g][SWZ(PIDX(yy, xx))];
        sp[g][SWZ(PIDX(y, x))] = s * (1.0f / (float)((y1 - y0 + 1) * (x1 - x0 + 1)));
    }
    __syncthreads();

    // Border-fill pooled planes.
    for (int t = tid; t < G * PSZ; t += 256) {
        int g = t / PSZ, j = t - g * PSZ;
        int py = j / PADW, px = j - py * PADW;
        if (px > PADH - 1) continue;
        int y = py - 3, x = px - 3;
        if ((unsigned)y < (unsigned)W && (unsigned)x < (unsigned)W) continue;
        sp[g][SWZ(j)] = sp[g][SWZ(PIDX(clampw(y), clampw(x)))];
    }
    __syncthreads();

    // Gather + store 17 bins per channel. Channel loop kept rolled for regs.
    #pragma unroll 1
    for (int g = 0; g < G; g++) {
        const float* __restrict__ a_r = sr[g];
        const float* __restrict__ a_p = sp[g];

        const size_t ob = ((size_t)(b * NBINS) * D + (c0 + g)) * PLANE;
        float* const obase = out + ob;
        const int phase = (int)(ob & 3);
        const int head  = (4 - phase) & 3;
        const int nq    = (PLANE - head) >> 2;
        const int tail  = (PLANE - head) & 3;

        // Body: 16B-aligned float4 quads (CHPLANE % 4 == 0 keeps all bins aligned).
        for (int q = tid; q < nq; q += 256) {
            const int i0 = head + 4 * q;
            int y0 = i0 / W, x0 = i0 - y0 * W;
            int be[4];
            #pragma unroll
            for (int e = 0; e < 4; e++) {
                int xi = x0 + e, yi = y0;
                if (xi >= W) { xi -= W; yi++; }        // at most one row crossing
                be[e] = PIDX(yi, xi);
            }

            #pragma unroll
            for (int bin = 0; bin < 17; bin++) {
                const float* a = (bin < 9) ? a_r : a_p;
                const int off = c_off[bin];
                float4 r;
                r.x = a[SWZ(be[0] + off)];
                r.y = a[SWZ(be[1] + off)];
                r.z = a[SWZ(be[2] + off)];
                r.w = a[SWZ(be[3] + off)];
                *reinterpret_cast<float4*>(obase + (size_t)bin * CHPLANE + i0) = r;
            }
        }

        // Head/tail scalars.
        int si = -1;
        if (tid < head)
            si = tid;
        else if (tid >= 32 && tid < 32 + tail)
            si = head + 4 * nq + (tid - 32);
        if (si >= 0) {
            int y = si / W, x = si - y * W;
            int base = PIDX(y, x);
            #pragma unroll
            for (int bin = 0; bin < 17; bin++) {
                const float* a = (bin < 9) ? a_r : a_p;
                obase[(size_t)bin * CHPLANE + si] = a[SWZ(base + c_off[bin])];
            }
        }
    }
}

// ---------------------------------------------------------------------------
extern "C" void kernel_launch(void* const* d_in, const int* in_sizes, int n_in,
                              void* d_out, int out_size) {
    const float* x = (const float*)d_in[0];
    float* out = (float*)d_out;
    fanout_kernel<<<NBLOCKS, 256>>>(x, out);
}